// round 2
// baseline (speedup 1.0000x reference)
#include <cuda_runtime.h>
#include <math.h>

#define BATCH 8
#define CDIM 192
#define C3 576
#define HEADS 8
#define CH 24
#define IMGH 128
#define IMGW 128
#define HW (IMGH * IMGW)

// ---------------- scratch (device globals; no allocation allowed) ----------------
__device__ float g_qkv[(size_t)BATCH * C3 * HW];    // 302 MB: qkv after 1x1 conv
__device__ float g_v[(size_t)BATCH * CDIM * HW];    // 100 MB: v after depthwise
__device__ float g_G[BATCH * HEADS * CH * CH];      // unnormalized gram
__device__ float g_nq[BATCH * HEADS * CH];          // sum qf^2
__device__ float g_nk[BATCH * HEADS * CH];          // sum kf^2
__device__ float g_M[BATCH * CDIM * CDIM];          // W_proj @ blockdiag(attn)

// ---------------- K0: zero accumulators ----------------
__global__ void zero_accum() {
    int i = blockIdx.x * blockDim.x + threadIdx.x;
    if (i < BATCH * HEADS * CH * CH) g_G[i] = 0.f;
    if (i < BATCH * HEADS * CH) { g_nq[i] = 0.f; g_nk[i] = 0.f; }
}

// ---------------- K1 / K4: batched GEMM  C[b] = A[b](Mrows x 192) @ B[b](192 x 16384)
// mode 0:  A = W_qkv (shared, aStride=0), B = x,   C = g_qkv   (Mrows=576)
// mode 1:  A = g_M   (aStride=192*192),   B = g_v, C = out     (Mrows=192)
// Block tile 64(M) x 128(N), K-chunk 16, thread tile 4x8, 256 threads.
__global__ void __launch_bounds__(256) gemm192(const float* __restrict__ Aext,
                                               const float* __restrict__ Bext,
                                               float* __restrict__ Cext,
                                               int Mrows, int aStride, int mode) {
    __shared__ float As[64 * 16];    // [o][k]
    __shared__ float Bs[16 * 128];   // [k][n]

    const float* A = (mode == 0) ? Aext : g_M;
    const float* B = (mode == 0) ? Bext : g_v;
    float* Cc      = (mode == 0) ? g_qkv : Cext;

    int b = blockIdx.z;
    const float* Ab = A + (size_t)b * aStride;
    const float* Bb = B + (size_t)b * CDIM * HW;
    float* Cb = Cc + (size_t)b * Mrows * HW;

    int o0 = blockIdx.y * 64;
    int n0 = blockIdx.x * 128;
    int t = threadIdx.x;
    int tx = t & 15, ty = t >> 4;

    float acc[4][8];
#pragma unroll
    for (int i = 0; i < 4; ++i)
#pragma unroll
        for (int j = 0; j < 8; ++j) acc[i][j] = 0.f;

    int ar = t >> 2, ac = t & 3;    // A-tile loader: row 0..63, float4 col 0..3
    int bk = t >> 5, bc = t & 31;   // B-tile loader: k row 0..7, float4 col 0..31

    for (int kb = 0; kb < CDIM; kb += 16) {
        float4 av = *(const float4*)(Ab + (size_t)(o0 + ar) * CDIM + kb + ac * 4);
        ((float4*)As)[ar * 4 + ac] = av;

        float4 bv0 = *(const float4*)(Bb + (size_t)(kb + bk) * HW + n0 + bc * 4);
        float4 bv1 = *(const float4*)(Bb + (size_t)(kb + bk + 8) * HW + n0 + bc * 4);
        ((float4*)Bs)[bk * 32 + bc] = bv0;
        ((float4*)Bs)[(bk + 8) * 32 + bc] = bv1;
        __syncthreads();

#pragma unroll
        for (int k = 0; k < 16; ++k) {
            float a[4], bb[8];
#pragma unroll
            for (int i = 0; i < 4; ++i) a[i] = As[(ty + 16 * i) * 16 + k];
#pragma unroll
            for (int j = 0; j < 8; ++j) bb[j] = Bs[k * 128 + tx + 16 * j];
#pragma unroll
            for (int i = 0; i < 4; ++i)
#pragma unroll
                for (int j = 0; j < 8; ++j) acc[i][j] = fmaf(a[i], bb[j], acc[i][j]);
        }
        __syncthreads();
    }

#pragma unroll
    for (int i = 0; i < 4; ++i)
#pragma unroll
        for (int j = 0; j < 8; ++j)
            Cb[(size_t)(o0 + ty + 16 * i) * HW + n0 + tx + 16 * j] = acc[i][j];
}

// ---------------- K2: depthwise 3x3 + f-mult + partial gram/norms + v write ----------------
__device__ __forceinline__ float dw3x3(const float* __restrict__ p, int y, int x,
                                       const float* __restrict__ w) {
    float s = 0.f;
#pragma unroll
    for (int ky = 0; ky < 3; ++ky) {
        int yy = y + ky - 1;
        if (yy < 0 || yy >= IMGH) continue;
#pragma unroll
        for (int kx = 0; kx < 3; ++kx) {
            int xx = x + kx - 1;
            if (xx < 0 || xx >= IMGW) continue;
            s = fmaf(p[yy * IMGW + xx], w[ky * 3 + kx], s);
        }
    }
    return s;
}

// grid: (8, 16, BATCH*HEADS), block 128.  Tile = 16 wide x 8 tall = 128 px.
__global__ void __launch_bounds__(128) k2_dw_gram(const float* __restrict__ feature,
                                                  const float* __restrict__ W_dw) {
    __shared__ float qf_s[128 * 24];    // [pixel][chan]
    __shared__ float kf_s[128 * 24];
    __shared__ float wdw_s[72 * 9];     // dw weights: q(24) k(24) v(24) for this head

    int bh = blockIdx.z;
    int b = bh >> 3;
    int hd = bh & 7;
    int t = threadIdx.x;

    // stage dw weights for this head's 72 channels
    for (int i = t; i < 72 * 9; i += 128) {
        int c = i / 9, r = i % 9;
        int part = c / 24;       // 0=q, 1=k, 2=v
        int cl = c % 24;
        wdw_s[i] = W_dw[(size_t)(part * CDIM + hd * CH + cl) * 9 + r];
    }
    __syncthreads();

    int px = t & 15, py = t >> 4;
    int x = blockIdx.x * 16 + px;
    int y = blockIdx.y * 8 + py;
    const size_t img = (size_t)HW;

#pragma unroll 1
    for (int c = 0; c < CH; ++c) {
        int cq = hd * CH + c;
        const float* qp = g_qkv + ((size_t)b * C3 + cq) * img;
        const float* kp = qp + (size_t)CDIM * img;
        const float* vp = qp + (size_t)(2 * CDIM) * img;
        float qv = dw3x3(qp, y, x, wdw_s + (0 * 24 + c) * 9);
        float kv = dw3x3(kp, y, x, wdw_s + (1 * 24 + c) * 9);
        float vv = dw3x3(vp, y, x, wdw_s + (2 * 24 + c) * 9);
        float f = feature[((size_t)b * CDIM + cq) * img + y * IMGW + x];
        qf_s[t * 24 + c] = qv * f;
        kf_s[t * 24 + c] = kv * f;
        g_v[((size_t)b * CDIM + cq) * img + y * IMGW + x] = vv;
    }
    __syncthreads();

    // squared-norm partials (threads 0..47)
    if (t < 48) {
        int c = t % 24;
        const float* src = (t < 24) ? qf_s : kf_s;
        float s = 0.f;
#pragma unroll 4
        for (int p = 0; p < 128; ++p) { float v = src[p * 24 + c]; s = fmaf(v, v, s); }
        atomicAdd(((t < 24) ? g_nq : g_nk) + bh * 24 + c, s);
    }

    // gram partials: 576 (c,d) entries over 128 threads
    for (int e = t; e < CH * CH; e += 128) {
        int cc = e / 24, dd = e % 24;
        float s = 0.f;
#pragma unroll 4
        for (int p = 0; p < 128; ++p)
            s = fmaf(qf_s[p * 24 + cc], kf_s[p * 24 + dd], s);
        atomicAdd(&g_G[bh * (CH * CH) + cc * 24 + dd], s);
    }
}

// ---------------- K3: softmax(attn) + M = W_proj @ blockdiag(attn) ----------------
// grid: 64 blocks (one per b,h), 192 threads.
__global__ void __launch_bounds__(192) k3_attn_M(const float* __restrict__ W_proj,
                                                 const float* __restrict__ temperature) {
    __shared__ float attn_s[24 * 24];
    int bh = blockIdx.x;
    int b = bh >> 3;
    int hd = bh & 7;
    int t = threadIdx.x;

    if (t < 24) {
        float inq = 1.f / fmaxf(sqrtf(g_nq[bh * 24 + t]), 1e-12f);
        float temp = temperature[hd];
        float row[24];
        float mx = -1e30f;
#pragma unroll
        for (int d = 0; d < 24; ++d) {
            float ink = 1.f / fmaxf(sqrtf(g_nk[bh * 24 + d]), 1e-12f);
            float v = g_G[bh * (CH * CH) + t * 24 + d] * inq * ink * temp;
            row[d] = v;
            mx = fmaxf(mx, v);
        }
        float sum = 0.f;
#pragma unroll
        for (int d = 0; d < 24; ++d) { row[d] = expf(row[d] - mx); sum += row[d]; }
        float inv = 1.f / sum;
#pragma unroll
        for (int d = 0; d < 24; ++d) attn_s[t * 24 + d] = row[d] * inv;
    }
    __syncthreads();

    // M[o][hd*24+d] = sum_cl W_proj[o][hd*24+cl] * attn[cl][d]
    float acc[24];
#pragma unroll
    for (int d = 0; d < 24; ++d) acc[d] = 0.f;
#pragma unroll 1
    for (int cl = 0; cl < 24; ++cl) {
        float w = W_proj[(size_t)t * CDIM + hd * CH + cl];
#pragma unroll
        for (int d = 0; d < 24; ++d) acc[d] = fmaf(w, attn_s[cl * 24 + d], acc[d]);
    }
#pragma unroll
    for (int d = 0; d < 24; ++d)
        g_M[((size_t)b * CDIM + t) * CDIM + hd * CH + d] = acc[d];
}

// ---------------- launch ----------------
extern "C" void kernel_launch(void* const* d_in, const int* in_sizes, int n_in,
                              void* d_out, int out_size) {
    const float* x           = (const float*)d_in[0];
    const float* feature     = (const float*)d_in[1];
    const float* W_qkv       = (const float*)d_in[2];
    const float* W_dw        = (const float*)d_in[3];
    const float* W_proj      = (const float*)d_in[4];
    const float* temperature = (const float*)d_in[5];
    float* out = (float*)d_out;

    zero_accum<<<144, 256>>>();

    // K1: qkv = W_qkv @ x   (576 x 16384 per batch)
    dim3 g1(HW / 128, C3 / 64, BATCH);
    gemm192<<<g1, 256>>>(W_qkv, x, nullptr, C3, 0, 0);

    // K2: depthwise + gram/norm partials + v
    dim3 g2(IMGW / 16, IMGH / 8, BATCH * HEADS);
    k2_dw_gram<<<g2, 128>>>(feature, W_dw);

    // K3: softmax + fold proj
    k3_attn_M<<<64, 192>>>(W_proj, temperature);

    // K4: out = M @ v   (192 x 16384 per batch)
    dim3 g4(HW / 128, CDIM / 64, BATCH);
    gemm192<<<g4, 256>>>(nullptr, nullptr, out, CDIM, CDIM * CDIM, 1);
}

// round 6
// speedup vs baseline: 1.0938x; 1.0938x over previous
#include <cuda_runtime.h>
#include <math.h>
#include <stdint.h>

#define BATCH 8
#define CDIM 192
#define C3 576
#define HEADS 8
#define CH 24
#define IMGH 128
#define IMGW 128
#define HW (IMGH * IMGW)

// ---------------- scratch (device globals; no allocation allowed) ----------------
__device__ float g_qkv[(size_t)BATCH * C3 * HW];    // qkv after 1x1 conv
__device__ float g_v[(size_t)BATCH * CDIM * HW];    // v after depthwise
__device__ float g_G[BATCH * HEADS * CH * CH];      // unnormalized gram
__device__ float g_nq[BATCH * HEADS * CH];          // sum qf^2
__device__ float g_nk[BATCH * HEADS * CH];          // sum kf^2
__device__ float g_M[BATCH * CDIM * CDIM];          // W_proj @ blockdiag(attn)

// ---------------- helpers ----------------
// cvt.rna.tf32.f32 requires a .b32 destination register in PTX ("=r", not "=f").
__device__ __forceinline__ float to_tf32(float x) {
    uint32_t r; asm("cvt.rna.tf32.f32 %0, %1;" : "=r"(r) : "f"(x));
    return __uint_as_float(r);
}
__device__ __forceinline__ uint32_t fu(float x) { return __float_as_uint(x); }

#define MMA_TF32(acc, a, b0r, b1r) \
    asm volatile("mma.sync.aligned.m16n8k8.row.col.f32.tf32.tf32.f32 " \
                 "{%0,%1,%2,%3},{%4,%5,%6,%7},{%8,%9},{%0,%1,%2,%3};" \
                 : "+f"((acc)[0]), "+f"((acc)[1]), "+f"((acc)[2]), "+f"((acc)[3]) \
                 : "r"((a)[0]), "r"((a)[1]), "r"((a)[2]), "r"((a)[3]), \
                   "r"(b0r), "r"(b1r))

// ---------------- K0: zero accumulators ----------------
__global__ void zero_accum() {
    int i = blockIdx.x * blockDim.x + threadIdx.x;
    if (i < BATCH * HEADS * CH * CH) g_G[i] = 0.f;
    if (i < BATCH * HEADS * CH) { g_nq[i] = 0.f; g_nk[i] = 0.f; }
}

// ---------------- K1 / K4: tf32 tensor-core GEMM  C[b] = A(Mx192) @ B[b](192x16384)
// mode 0: A = W_qkv (aStride 0), B = x,  C = g_qkv.  Rows >= 384 (v) use 3xTF32.
// mode 1: A = g_M,               B = g_v, C = out.   All rows 3xTF32.
// Block tile 64(M) x 128(N), K-chunk 16, 256 threads = 8 warps (2Mx4N), warp tile 32x32.
__global__ void __launch_bounds__(256) gemm_tf32(const float* __restrict__ Aext,
                                                 const float* __restrict__ Bext,
                                                 float* __restrict__ Cext,
                                                 int Mrows, int aStride, int mode) {
    __shared__ float Ah[64 * 20], Al[64 * 20];      // [m][k] stride 20 (bank-clean frags)
    __shared__ float Bh[16 * 136], Bl[16 * 136];    // [k][n] stride 136 (bank-clean frags)

    const float* A = (mode == 0) ? Aext : g_M;
    const float* B = (mode == 0) ? Bext : g_v;
    float* Cc      = (mode == 0) ? g_qkv : Cext;

    int b = blockIdx.z;
    const float* Ab = A + (size_t)b * aStride;
    const float* Bb = B + (size_t)b * CDIM * HW;
    float* Cb = Cc + (size_t)b * Mrows * HW;

    int o0 = blockIdx.y * 64;
    int n0 = blockIdx.x * 128;
    const bool triple = (mode == 1) || (o0 >= 2 * CDIM);

    int t = threadIdx.x;
    int lane = t & 31, wid = t >> 5;
    int wm = wid >> 2, wn = wid & 3;    // warp grid 2(M) x 4(N)

    float acc[2][4][4];
#pragma unroll
    for (int mi = 0; mi < 2; ++mi)
#pragma unroll
        for (int ni = 0; ni < 4; ++ni)
#pragma unroll
            for (int r = 0; r < 4; ++r) acc[mi][ni][r] = 0.f;

    int ar = t >> 2, ac4 = t & 3;   // A loader: row 0..63, float4 col 0..3
    int bk = t >> 5, bc = t & 31;   // B loader: k rows bk, bk+8; float4 col 0..31

    for (int kb = 0; kb < CDIM; kb += 16) {
        // ---- stage A chunk (64x16) with tf32 hi/lo split ----
        float4 av = *(const float4*)(Ab + (size_t)(o0 + ar) * CDIM + kb + ac4 * 4);
        {
            float* ap = (float*)&av;
#pragma unroll
            for (int j = 0; j < 4; ++j) {
                float hi = to_tf32(ap[j]);
                Ah[ar * 20 + ac4 * 4 + j] = hi;
                Al[ar * 20 + ac4 * 4 + j] = to_tf32(ap[j] - hi);
            }
        }
        // ---- stage B chunk (16x128) ----
        float4 bv0 = *(const float4*)(Bb + (size_t)(kb + bk) * HW + n0 + bc * 4);
        float4 bv1 = *(const float4*)(Bb + (size_t)(kb + bk + 8) * HW + n0 + bc * 4);
        {
            float4 h0, l0, h1, l1;
            float* s0 = (float*)&bv0; float* s1 = (float*)&bv1;
            float* ph0 = (float*)&h0; float* pl0 = (float*)&l0;
            float* ph1 = (float*)&h1; float* pl1 = (float*)&l1;
#pragma unroll
            for (int j = 0; j < 4; ++j) {
                ph0[j] = to_tf32(s0[j]); pl0[j] = to_tf32(s0[j] - ph0[j]);
                ph1[j] = to_tf32(s1[j]); pl1[j] = to_tf32(s1[j] - ph1[j]);
            }
            *(float4*)&Bh[bk * 136 + bc * 4] = h0;
            *(float4*)&Bl[bk * 136 + bc * 4] = l0;
            *(float4*)&Bh[(bk + 8) * 136 + bc * 4] = h1;
            *(float4*)&Bl[(bk + 8) * 136 + bc * 4] = l1;
        }
        __syncthreads();

#pragma unroll
        for (int ks = 0; ks < 2; ++ks) {
            int k0 = ks * 8;
            uint32_t ah[2][4], al[2][4];
#pragma unroll
            for (int mi = 0; mi < 2; ++mi) {
                int mr = wm * 32 + mi * 16 + (lane >> 2);
                int kc = k0 + (lane & 3);
                ah[mi][0] = fu(Ah[mr * 20 + kc]);
                ah[mi][1] = fu(Ah[(mr + 8) * 20 + kc]);
                ah[mi][2] = fu(Ah[mr * 20 + kc + 4]);
                ah[mi][3] = fu(Ah[(mr + 8) * 20 + kc + 4]);
                if (triple) {
                    al[mi][0] = fu(Al[mr * 20 + kc]);
                    al[mi][1] = fu(Al[(mr + 8) * 20 + kc]);
                    al[mi][2] = fu(Al[mr * 20 + kc + 4]);
                    al[mi][3] = fu(Al[(mr + 8) * 20 + kc + 4]);
                }
            }
#pragma unroll
            for (int ni = 0; ni < 4; ++ni) {
                int bn = wn * 32 + ni * 8 + (lane >> 2);
                int kr = k0 + (lane & 3);
                uint32_t bh0 = fu(Bh[kr * 136 + bn]);
                uint32_t bh1 = fu(Bh[(kr + 4) * 136 + bn]);
#pragma unroll
                for (int mi = 0; mi < 2; ++mi)
                    MMA_TF32(acc[mi][ni], ah[mi], bh0, bh1);
                if (triple) {
                    uint32_t bl0 = fu(Bl[kr * 136 + bn]);
                    uint32_t bl1 = fu(Bl[(kr + 4) * 136 + bn]);
#pragma unroll
                    for (int mi = 0; mi < 2; ++mi) {
                        MMA_TF32(acc[mi][ni], al[mi], bh0, bh1);
                        MMA_TF32(acc[mi][ni], ah[mi], bl0, bl1);
                    }
                }
            }
        }
        __syncthreads();
    }

    // ---- epilogue ----
#pragma unroll
    for (int mi = 0; mi < 2; ++mi) {
        int r0 = o0 + wm * 32 + mi * 16 + (lane >> 2);
#pragma unroll
        for (int ni = 0; ni < 4; ++ni) {
            int cc = n0 + wn * 32 + ni * 8 + (lane & 3) * 2;
            float2 v01 = make_float2(acc[mi][ni][0], acc[mi][ni][1]);
            float2 v23 = make_float2(acc[mi][ni][2], acc[mi][ni][3]);
            *(float2*)(Cb + (size_t)r0 * HW + cc) = v01;
            *(float2*)(Cb + (size_t)(r0 + 8) * HW + cc) = v23;
        }
    }
}

// ---------------- K2: depthwise 3x3 (smem-staged) + f-mult + tensor gram + norms + v ----------------
// grid: (8, 16, 64) = 8192 blocks, 128 threads (4 warps). Tile 16 wide x 8 tall.
__global__ void __launch_bounds__(128) k2_dw_gram(const float* __restrict__ feature,
                                                  const float* __restrict__ W_dw) {
    __shared__ float stage[3 * 10 * 20];            // q,k,v halo tiles of current channel
    __shared__ float qf_s[128 * 25 + 8];            // [px][ch], stride 25, tf32-rounded
    __shared__ float kf_s[128 * 25 + 8];
    __shared__ float wdw_s[72 * 9];
    __shared__ float gram_s[CH * CH];

    int bh = blockIdx.z;
    int b = bh >> 3;
    int hd = bh & 7;
    int t = threadIdx.x;
    int lane = t & 31, wid = t >> 5;

    for (int i = t; i < 72 * 9; i += 128) {
        int c = i / 9, r = i % 9;
        int part = c / 24, cl = c % 24;
        wdw_s[i] = W_dw[(size_t)(part * CDIM + hd * CH + cl) * 9 + r];
    }
    for (int i = t; i < CH * CH; i += 128) gram_s[i] = 0.f;
    // clear the unused 25th column so garbage never enters smem reads
    qf_s[t * 25 + 24] = 0.f;
    kf_s[t * 25 + 24] = 0.f;

    int px = t & 15, py = t >> 4;
    int x0 = blockIdx.x * 16, y0 = blockIdx.y * 8;
    const size_t img = (size_t)HW;

    for (int c = 0; c < CH; ++c) {
        __syncthreads();   // protect stage from previous iteration's readers
        int cq = hd * CH + c;
        const float* qp = g_qkv + ((size_t)b * C3 + cq) * img;
        // stage 3 halo tiles (10 x 18 each)
        for (int i = t; i < 540; i += 128) {
            int p = i / 180, rem = i % 180;
            int sy = rem / 18, sx = rem % 18;
            int gy = y0 - 1 + sy, gx = x0 - 1 + sx;
            float v = 0.f;
            if (gy >= 0 && gy < IMGH && gx >= 0 && gx < IMGW)
                v = qp[(size_t)p * CDIM * img + gy * IMGW + gx];
            stage[p * 200 + sy * 20 + sx] = v;
        }
        __syncthreads();

        float q = 0.f, k = 0.f, v = 0.f;
        const float* wq = wdw_s + (0 * 24 + c) * 9;
        const float* wk = wdw_s + (1 * 24 + c) * 9;
        const float* wv = wdw_s + (2 * 24 + c) * 9;
#pragma unroll
        for (int ky = 0; ky < 3; ++ky)
#pragma unroll
            for (int kx = 0; kx < 3; ++kx) {
                int si = (py + ky) * 20 + px + kx;
                float sq = stage[si], sk = stage[200 + si], sv = stage[400 + si];
                q = fmaf(sq, wq[ky * 3 + kx], q);
                k = fmaf(sk, wk[ky * 3 + kx], k);
                v = fmaf(sv, wv[ky * 3 + kx], v);
            }
        float f = feature[((size_t)b * CDIM + cq) * img + (y0 + py) * IMGW + x0 + px];
        qf_s[t * 25 + c] = to_tf32(q * f);
        kf_s[t * 25 + c] = to_tf32(k * f);
        g_v[((size_t)b * CDIM + cq) * img + (y0 + py) * IMGW + x0 + px] = v;
    }
    __syncthreads();

    // squared-norm partials (exact on the tf32-rounded values -> consistent with gram)
    if (t < 48) {
        int c = t % 24;
        const float* src = (t < 24) ? qf_s : kf_s;
        float s = 0.f;
#pragma unroll 4
        for (int p = 0; p < 128; ++p) { float vv = src[p * 25 + c]; s = fmaf(vv, vv, s); }
        atomicAdd(((t < 24) ? g_nq : g_nk) + bh * 24 + c, s);
    }

    // gram via tf32 MMA: G[c][d] += sum_px qf[px][c] * kf[px][d]
    // warp w handles px range [32w, 32w+32): 4 k-steps of 8
    float g[2][3][4];
#pragma unroll
    for (int mi = 0; mi < 2; ++mi)
#pragma unroll
        for (int ni = 0; ni < 3; ++ni)
#pragma unroll
            for (int r = 0; r < 4; ++r) g[mi][ni][r] = 0.f;

#pragma unroll
    for (int ks = 0; ks < 4; ++ks) {
        int pxb = wid * 32 + ks * 8;
        int pxl = pxb + (lane & 3);
        uint32_t a[2][4], bb[3][2];
#pragma unroll
        for (int mi = 0; mi < 2; ++mi) {
            int cc = mi * 16 + (lane >> 2);
            a[mi][0] = fu(qf_s[pxl * 25 + cc]);
            a[mi][1] = fu(qf_s[pxl * 25 + cc + 8]);
            a[mi][2] = fu(qf_s[(pxl + 4) * 25 + cc]);
            a[mi][3] = fu(qf_s[(pxl + 4) * 25 + cc + 8]);
        }
#pragma unroll
        for (int ni = 0; ni < 3; ++ni) {
            int dd = ni * 8 + (lane >> 2);
            bb[ni][0] = fu(kf_s[pxl * 25 + dd]);
            bb[ni][1] = fu(kf_s[(pxl + 4) * 25 + dd]);
        }
#pragma unroll
        for (int mi = 0; mi < 2; ++mi)
#pragma unroll
            for (int ni = 0; ni < 3; ++ni)
                MMA_TF32(g[mi][ni], a[mi], bb[ni][0], bb[ni][1]);
    }

    // reduce warp partials into gram_s (rows >= 24 are padding -> dropped)
#pragma unroll
    for (int mi = 0; mi < 2; ++mi) {
        int r0 = mi * 16 + (lane >> 2);
#pragma unroll
        for (int ni = 0; ni < 3; ++ni) {
            int c0 = ni * 8 + (lane & 3) * 2;
            if (r0 < 24) {
                atomicAdd(&gram_s[r0 * 24 + c0], g[mi][ni][0]);
                atomicAdd(&gram_s[r0 * 24 + c0 + 1], g[mi][ni][1]);
            }
            if (r0 + 8 < 24) {
                atomicAdd(&gram_s[(r0 + 8) * 24 + c0], g[mi][ni][2]);
                atomicAdd(&gram_s[(r0 + 8) * 24 + c0 + 1], g[mi][ni][3]);
            }
        }
    }
    __syncthreads();
    for (int e = t; e < CH * CH; e += 128)
        atomicAdd(&g_G[bh * (CH * CH) + e], gram_s[e]);
}

// ---------------- K3: softmax(attn) + M = W_proj @ blockdiag(attn) ----------------
__global__ void __launch_bounds__(192) k3_attn_M(const float* __restrict__ W_proj,
                                                 const float* __restrict__ temperature) {
    __shared__ float attn_s[24 * 24];
    int bh = blockIdx.x;
    int b = bh >> 3;
    int hd = bh & 7;
    int t = threadIdx.x;

    if (t < 24) {
        float inq = 1.f / fmaxf(sqrtf(g_nq[bh * 24 + t]), 1e-12f);
        float temp = temperature[hd];
        float row[24];
        float mx = -1e30f;
#pragma unroll
        for (int d = 0; d < 24; ++d) {
            float ink = 1.f / fmaxf(sqrtf(g_nk[bh * 24 + d]), 1e-12f);
            float v = g_G[bh * (CH * CH) + t * 24 + d] * inq * ink * temp;
            row[d] = v;
            mx = fmaxf(mx, v);
        }
        float sum = 0.f;
#pragma unroll
        for (int d = 0; d < 24; ++d) { row[d] = expf(row[d] - mx); sum += row[d]; }
        float inv = 1.f / sum;
#pragma unroll
        for (int d = 0; d < 24; ++d) attn_s[t * 24 + d] = row[d] * inv;
    }
    __syncthreads();

    float acc[24];
#pragma unroll
    for (int d = 0; d < 24; ++d) acc[d] = 0.f;
#pragma unroll 1
    for (int cl = 0; cl < 24; ++cl) {
        float w = W_proj[(size_t)t * CDIM + hd * CH + cl];
#pragma unroll
        for (int d = 0; d < 24; ++d) acc[d] = fmaf(w, attn_s[cl * 24 + d], acc[d]);
    }
#pragma unroll
    for (int d = 0; d < 24; ++d)
        g_M[((size_t)b * CDIM + t) * CDIM + hd * CH + d] = acc[d];
}

// ---------------- launch ----------------
extern "C" void kernel_launch(void* const* d_in, const int* in_sizes, int n_in,
                              void* d_out, int out_size) {
    const float* x           = (const float*)d_in[0];
    const float* feature     = (const float*)d_in[1];
    const float* W_qkv       = (const float*)d_in[2];
    const float* W_dw        = (const float*)d_in[3];
    const float* W_proj      = (const float*)d_in[4];
    const float* temperature = (const float*)d_in[5];
    float* out = (float*)d_out;

    zero_accum<<<144, 256>>>();

    // K1: qkv = W_qkv @ x   (576 x 16384 per batch)
    dim3 g1(HW / 128, C3 / 64, BATCH);
    gemm_tf32<<<g1, 256>>>(W_qkv, x, nullptr, C3, 0, 0);

    // K2: depthwise + gram/norm partials + v
    dim3 g2(IMGW / 16, IMGH / 8, BATCH * HEADS);
    k2_dw_gram<<<g2, 128>>>(feature, W_dw);

    // K3: softmax + fold proj
    k3_attn_M<<<64, 192>>>(W_proj, temperature);

    // K4: out = M @ v   (192 x 16384 per batch)
    dim3 g4(HW / 128, CDIM / 64, BATCH);
    gemm_tf32<<<g4, 256>>>(nullptr, nullptr, out, CDIM, CDIM * CDIM, 1);
}

// round 8
// speedup vs baseline: 1.5024x; 1.3735x over previous
#include <cuda_runtime.h>
#include <math.h>
#include <stdint.h>

#define BATCH 8
#define CDIM 192
#define C3 576
#define HEADS 8
#define CH 24
#define IMGH 128
#define IMGW 128
#define HW (IMGH * IMGW)

// ---------------- scratch (device globals; no allocation allowed) ----------------
__device__ float g_qkv[(size_t)BATCH * C3 * HW];
__device__ float g_v[(size_t)BATCH * CDIM * HW];
__device__ float g_G[BATCH * HEADS * CH * CH];
__device__ float g_nq[BATCH * HEADS * CH];
__device__ float g_nk[BATCH * HEADS * CH];
__device__ float g_M[BATCH * CDIM * CDIM];

// ---------------- helpers ----------------
__device__ __forceinline__ float to_tf32(float x) {
    uint32_t r; asm("cvt.rna.tf32.f32 %0, %1;" : "=r"(r) : "f"(x));
    return __uint_as_float(r);
}
__device__ __forceinline__ uint32_t fu(float x) { return __float_as_uint(x); }

#define MMA_TF32(acc, a, b0r, b1r) \
    asm volatile("mma.sync.aligned.m16n8k8.row.col.f32.tf32.tf32.f32 " \
                 "{%0,%1,%2,%3},{%4,%5,%6,%7},{%8,%9},{%0,%1,%2,%3};" \
                 : "+f"((acc)[0]), "+f"((acc)[1]), "+f"((acc)[2]), "+f"((acc)[3]) \
                 : "r"((a)[0]), "r"((a)[1]), "r"((a)[2]), "r"((a)[3]), \
                   "r"(b0r), "r"(b1r))

// ---------------- K0: zero accumulators ----------------
__global__ void zero_accum() {
    int i = blockIdx.x * blockDim.x + threadIdx.x;
    if (i < BATCH * HEADS * CH * CH) g_G[i] = 0.f;
    if (i < BATCH * HEADS * CH) { g_nq[i] = 0.f; g_nk[i] = 0.f; }
}

// ---------------- K1a: q,k rows (0..383) single tf32, double-buffered smem ----------------
// Block tile 64M x 128N, K-chunk 16, 256 threads = 8 warps (2Mx4N).
__global__ void __launch_bounds__(256) gemm_qk(const float* __restrict__ W,
                                               const float* __restrict__ x) {
    __shared__ float Ah[2][64 * 20];
    __shared__ float Bh[2][16 * 136];

    int b = blockIdx.z;
    const float* Bb = x + (size_t)b * CDIM * HW;
    float* Cb = g_qkv + (size_t)b * C3 * HW;

    int o0 = blockIdx.y * 64;
    int n0 = blockIdx.x * 128;
    int t = threadIdx.x, lane = t & 31, wid = t >> 5;
    int wm = wid >> 2, wn = wid & 3;

    float acc[2][4][4];
#pragma unroll
    for (int mi = 0; mi < 2; ++mi)
#pragma unroll
        for (int ni = 0; ni < 4; ++ni)
#pragma unroll
            for (int r = 0; r < 4; ++r) acc[mi][ni][r] = 0.f;

    int ar = t >> 2, ac4 = t & 3;
    int bk = t >> 5, bc = t & 31;

    const float* Ap = W + (size_t)(o0 + ar) * CDIM + ac4 * 4;
    float4 avR = *(const float4*)Ap;
    float4 b0R = *(const float4*)(Bb + (size_t)bk * HW + n0 + bc * 4);
    float4 b1R = *(const float4*)(Bb + (size_t)(bk + 8) * HW + n0 + bc * 4);

    for (int kb = 0; kb < 12; ++kb) {
        int buf = kb & 1;
        {
            float* ap = (float*)&avR;
#pragma unroll
            for (int j = 0; j < 4; ++j) Ah[buf][ar * 20 + ac4 * 4 + j] = to_tf32(ap[j]);
            float4 h0, h1;
            float* s0 = (float*)&b0R; float* s1 = (float*)&b1R;
            float* p0 = (float*)&h0;  float* p1 = (float*)&h1;
#pragma unroll
            for (int j = 0; j < 4; ++j) { p0[j] = to_tf32(s0[j]); p1[j] = to_tf32(s1[j]); }
            *(float4*)&Bh[buf][bk * 136 + bc * 4] = h0;
            *(float4*)&Bh[buf][(bk + 8) * 136 + bc * 4] = h1;
        }
        __syncthreads();
        if (kb < 11) {   // prefetch next chunk into registers (overlaps MMA below)
            int k1 = (kb + 1) * 16;
            avR = *(const float4*)(Ap + k1);
            b0R = *(const float4*)(Bb + (size_t)(k1 + bk) * HW + n0 + bc * 4);
            b1R = *(const float4*)(Bb + (size_t)(k1 + bk + 8) * HW + n0 + bc * 4);
        }
#pragma unroll
        for (int ks = 0; ks < 2; ++ks) {
            int k0 = ks * 8;
            uint32_t ah[2][4];
#pragma unroll
            for (int mi = 0; mi < 2; ++mi) {
                int mr = wm * 32 + mi * 16 + (lane >> 2);
                int kc = k0 + (lane & 3);
                ah[mi][0] = fu(Ah[buf][mr * 20 + kc]);
                ah[mi][1] = fu(Ah[buf][(mr + 8) * 20 + kc]);
                ah[mi][2] = fu(Ah[buf][mr * 20 + kc + 4]);
                ah[mi][3] = fu(Ah[buf][(mr + 8) * 20 + kc + 4]);
            }
#pragma unroll
            for (int ni = 0; ni < 4; ++ni) {
                int bn = wn * 32 + ni * 8 + (lane >> 2);
                int kr = k0 + (lane & 3);
                uint32_t bh0 = fu(Bh[buf][kr * 136 + bn]);
                uint32_t bh1 = fu(Bh[buf][(kr + 4) * 136 + bn]);
#pragma unroll
                for (int mi = 0; mi < 2; ++mi)
                    MMA_TF32(acc[mi][ni], ah[mi], bh0, bh1);
            }
        }
        // no trailing sync: next iteration stores into the other buffer
    }

#pragma unroll
    for (int mi = 0; mi < 2; ++mi) {
        int r0 = o0 + wm * 32 + mi * 16 + (lane >> 2);
#pragma unroll
        for (int ni = 0; ni < 4; ++ni) {
            int cc = n0 + wn * 32 + ni * 8 + (lane & 3) * 2;
            *(float2*)(Cb + (size_t)r0 * HW + cc) = make_float2(acc[mi][ni][0], acc[mi][ni][1]);
            *(float2*)(Cb + (size_t)(r0 + 8) * HW + cc) = make_float2(acc[mi][ni][2], acc[mi][ni][3]);
        }
    }
}

// ---------------- K1b / K4: 3xTF32 GEMM (192 rows), register-prefetch pipeline ----------------
// mode 0: A = Aext (= W_qkv v-rows), B = Bext (= x), C = g_qkv rows 384..575
// mode 1: A = g_M[b],                B = g_v,        C = Cext (= out)
__global__ void __launch_bounds__(256) gemm_triple(int mode, const float* __restrict__ Aext,
                                                   const float* __restrict__ Bext,
                                                   float* __restrict__ Cext) {
    __shared__ float Ah[64 * 20], Al[64 * 20];
    __shared__ float Bhs[16 * 136], Bls[16 * 136];

    int b = blockIdx.z;
    const float* Ab = mode ? (g_M + (size_t)b * CDIM * CDIM) : Aext;
    const float* Bb = (mode ? (const float*)g_v : Bext) + (size_t)b * CDIM * HW;
    float* Cb = mode ? (Cext + (size_t)b * CDIM * HW)
                     : (g_qkv + (size_t)b * C3 * HW + (size_t)384 * HW);

    int o0 = blockIdx.y * 64;
    int n0 = blockIdx.x * 128;
    int t = threadIdx.x, lane = t & 31, wid = t >> 5;
    int wm = wid >> 2, wn = wid & 3;

    float acc[2][4][4];
#pragma unroll
    for (int mi = 0; mi < 2; ++mi)
#pragma unroll
        for (int ni = 0; ni < 4; ++ni)
#pragma unroll
            for (int r = 0; r < 4; ++r) acc[mi][ni][r] = 0.f;

    int ar = t >> 2, ac4 = t & 3;
    int bk = t >> 5, bc = t & 31;

    const float* Ap = Ab + (size_t)(o0 + ar) * CDIM + ac4 * 4;
    float4 avR = *(const float4*)Ap;
    float4 b0R = *(const float4*)(Bb + (size_t)bk * HW + n0 + bc * 4);
    float4 b1R = *(const float4*)(Bb + (size_t)(bk + 8) * HW + n0 + bc * 4);

    for (int kb = 0; kb < 12; ++kb) {
        {
            float* ap = (float*)&avR;
#pragma unroll
            for (int j = 0; j < 4; ++j) {
                float hi = to_tf32(ap[j]);
                Ah[ar * 20 + ac4 * 4 + j] = hi;
                Al[ar * 20 + ac4 * 4 + j] = to_tf32(ap[j] - hi);
            }
            float4 h0, l0, h1, l1;
            float* s0 = (float*)&b0R; float* s1 = (float*)&b1R;
            float* ph0 = (float*)&h0; float* pl0 = (float*)&l0;
            float* ph1 = (float*)&h1; float* pl1 = (float*)&l1;
#pragma unroll
            for (int j = 0; j < 4; ++j) {
                ph0[j] = to_tf32(s0[j]); pl0[j] = to_tf32(s0[j] - ph0[j]);
                ph1[j] = to_tf32(s1[j]); pl1[j] = to_tf32(s1[j] - ph1[j]);
            }
            *(float4*)&Bhs[bk * 136 + bc * 4] = h0;
            *(float4*)&Bls[bk * 136 + bc * 4] = l0;
            *(float4*)&Bhs[(bk + 8) * 136 + bc * 4] = h1;
            *(float4*)&Bls[(bk + 8) * 136 + bc * 4] = l1;
        }
        __syncthreads();
        if (kb < 11) {   // prefetch next chunk (overlaps MMA)
            int k1 = (kb + 1) * 16;
            avR = *(const float4*)(Ap + k1);
            b0R = *(const float4*)(Bb + (size_t)(k1 + bk) * HW + n0 + bc * 4);
            b1R = *(const float4*)(Bb + (size_t)(k1 + bk + 8) * HW + n0 + bc * 4);
        }
#pragma unroll
        for (int ks = 0; ks < 2; ++ks) {
            int k0 = ks * 8;
            uint32_t ah[2][4], al[2][4];
#pragma unroll
            for (int mi = 0; mi < 2; ++mi) {
                int mr = wm * 32 + mi * 16 + (lane >> 2);
                int kc = k0 + (lane & 3);
                ah[mi][0] = fu(Ah[mr * 20 + kc]);
                ah[mi][1] = fu(Ah[(mr + 8) * 20 + kc]);
                ah[mi][2] = fu(Ah[mr * 20 + kc + 4]);
                ah[mi][3] = fu(Ah[(mr + 8) * 20 + kc + 4]);
                al[mi][0] = fu(Al[mr * 20 + kc]);
                al[mi][1] = fu(Al[(mr + 8) * 20 + kc]);
                al[mi][2] = fu(Al[mr * 20 + kc + 4]);
                al[mi][3] = fu(Al[(mr + 8) * 20 + kc + 4]);
            }
#pragma unroll
            for (int ni = 0; ni < 4; ++ni) {
                int bn = wn * 32 + ni * 8 + (lane >> 2);
                int kr = k0 + (lane & 3);
                uint32_t bh0 = fu(Bhs[kr * 136 + bn]);
                uint32_t bh1 = fu(Bhs[(kr + 4) * 136 + bn]);
                uint32_t bl0 = fu(Bls[kr * 136 + bn]);
                uint32_t bl1 = fu(Bls[(kr + 4) * 136 + bn]);
#pragma unroll
                for (int mi = 0; mi < 2; ++mi) {
                    MMA_TF32(acc[mi][ni], ah[mi], bh0, bh1);
                    MMA_TF32(acc[mi][ni], al[mi], bh0, bh1);
                    MMA_TF32(acc[mi][ni], ah[mi], bl0, bl1);
                }
            }
        }
        __syncthreads();   // single smem buffer: protect against next store
    }

#pragma unroll
    for (int mi = 0; mi < 2; ++mi) {
        int r0 = o0 + wm * 32 + mi * 16 + (lane >> 2);
#pragma unroll
        for (int ni = 0; ni < 4; ++ni) {
            int cc = n0 + wn * 32 + ni * 8 + (lane & 3) * 2;
            *(float2*)(Cb + (size_t)r0 * HW + cc) = make_float2(acc[mi][ni][0], acc[mi][ni][1]);
            *(float2*)(Cb + (size_t)(r0 + 8) * HW + cc) = make_float2(acc[mi][ni][2], acc[mi][ni][3]);
        }
    }
}

// ---------------- K2: depthwise 3x3 + f-mult + tensor gram + norms + v ----------------
// 6 channels staged per round (4 rounds, 8 syncs) for high MLP.
// grid: (8, 16, 64), 128 threads (4 warps). Tile 16 wide x 8 tall.
__global__ void __launch_bounds__(128) k2_dw_gram(const float* __restrict__ feature,
                                                  const float* __restrict__ W_dw) {
    __shared__ float stage[3 * 6 * 200];   // [plane][ci][10][20] for 6 channels
    __shared__ float qf_s[128 * 25 + 8];
    __shared__ float kf_s[128 * 25 + 8];
    __shared__ float wdw_s[72 * 9];
    __shared__ float gram_s[CH * CH];

    int bh = blockIdx.z;
    int b = bh >> 3;
    int hd = bh & 7;
    int t = threadIdx.x;
    int lane = t & 31, wid = t >> 5;

    for (int i = t; i < 72 * 9; i += 128) {
        int c = i / 9, r = i % 9;
        int part = c / 24, cl = c % 24;
        wdw_s[i] = W_dw[(size_t)(part * CDIM + hd * CH + cl) * 9 + r];
    }
    for (int i = t; i < CH * CH; i += 128) gram_s[i] = 0.f;
    qf_s[t * 25 + 24] = 0.f;
    kf_s[t * 25 + 24] = 0.f;

    int px = t & 15, py = t >> 4;
    int x0 = blockIdx.x * 16, y0 = blockIdx.y * 8;
    const size_t img = (size_t)HW;

    for (int r = 0; r < 4; ++r) {
        int c0 = r * 6;
        __syncthreads();   // protect stage from previous round's readers
        // stage 3 planes x 6 channels of 10x18 halo tiles (3240 elems, ~25 LDG/thread in flight)
        for (int i = t; i < 3240; i += 128) {
            int p = i / 1080, rem = i % 1080;
            int ci = rem / 180, e = rem % 180;
            int sy = e / 18, sx = e % 18;
            int gy = y0 - 1 + sy, gx = x0 - 1 + sx;
            float v = 0.f;
            if (gy >= 0 && gy < IMGH && gx >= 0 && gx < IMGW)
                v = g_qkv[((size_t)b * C3 + p * CDIM + hd * CH + c0 + ci) * img + gy * IMGW + gx];
            stage[(p * 6 + ci) * 200 + sy * 20 + sx] = v;
        }
        __syncthreads();

#pragma unroll
        for (int ci = 0; ci < 6; ++ci) {
            int c = c0 + ci;
            float q = 0.f, k = 0.f, v = 0.f;
            const float* wq = wdw_s + (0 * 24 + c) * 9;
            const float* wk = wdw_s + (1 * 24 + c) * 9;
            const float* wv = wdw_s + (2 * 24 + c) * 9;
            const float* sq = stage + (0 * 6 + ci) * 200;
            const float* sk = stage + (1 * 6 + ci) * 200;
            const float* sv = stage + (2 * 6 + ci) * 200;
#pragma unroll
            for (int ky = 0; ky < 3; ++ky)
#pragma unroll
                for (int kx = 0; kx < 3; ++kx) {
                    int si = (py + ky) * 20 + px + kx;
                    q = fmaf(sq[si], wq[ky * 3 + kx], q);
                    k = fmaf(sk[si], wk[ky * 3 + kx], k);
                    v = fmaf(sv[si], wv[ky * 3 + kx], v);
                }
            int cq = hd * CH + c;
            float f = feature[((size_t)b * CDIM + cq) * img + (y0 + py) * IMGW + x0 + px];
            qf_s[t * 25 + c] = to_tf32(q * f);
            kf_s[t * 25 + c] = to_tf32(k * f);
            g_v[((size_t)b * CDIM + cq) * img + (y0 + py) * IMGW + x0 + px] = v;
        }
    }
    __syncthreads();

    // squared-norm partials
    if (t < 48) {
        int c = t % 24;
        const float* src = (t < 24) ? qf_s : kf_s;
        float s = 0.f;
#pragma unroll 4
        for (int p = 0; p < 128; ++p) { float vv = src[p * 25 + c]; s = fmaf(vv, vv, s); }
        atomicAdd(((t < 24) ? g_nq : g_nk) + bh * 24 + c, s);
    }

    // gram via tf32 MMA: G[c][d] += sum_px qf[px][c] * kf[px][d]
    float g[2][3][4];
#pragma unroll
    for (int mi = 0; mi < 2; ++mi)
#pragma unroll
        for (int ni = 0; ni < 3; ++ni)
#pragma unroll
            for (int r = 0; r < 4; ++r) g[mi][ni][r] = 0.f;

#pragma unroll
    for (int ks = 0; ks < 4; ++ks) {
        int pxb = wid * 32 + ks * 8;
        int pxl = pxb + (lane & 3);
        uint32_t a[2][4], bb[3][2];
#pragma unroll
        for (int mi = 0; mi < 2; ++mi) {
            int cc = mi * 16 + (lane >> 2);
            a[mi][0] = fu(qf_s[pxl * 25 + cc]);
            a[mi][1] = fu(qf_s[pxl * 25 + cc + 8]);
            a[mi][2] = fu(qf_s[(pxl + 4) * 25 + cc]);
            a[mi][3] = fu(qf_s[(pxl + 4) * 25 + cc + 8]);
        }
#pragma unroll
        for (int ni = 0; ni < 3; ++ni) {
            int dd = ni * 8 + (lane >> 2);
            bb[ni][0] = fu(kf_s[pxl * 25 + dd]);
            bb[ni][1] = fu(kf_s[(pxl + 4) * 25 + dd]);
        }
#pragma unroll
        for (int mi = 0; mi < 2; ++mi)
#pragma unroll
            for (int ni = 0; ni < 3; ++ni)
                MMA_TF32(g[mi][ni], a[mi], bb[ni][0], bb[ni][1]);
    }

#pragma unroll
    for (int mi = 0; mi < 2; ++mi) {
        int r0 = mi * 16 + (lane >> 2);
#pragma unroll
        for (int ni = 0; ni < 3; ++ni) {
            int c0 = ni * 8 + (lane & 3) * 2;
            if (r0 < 24) {
                atomicAdd(&gram_s[r0 * 24 + c0], g[mi][ni][0]);
                atomicAdd(&gram_s[r0 * 24 + c0 + 1], g[mi][ni][1]);
            }
            if (r0 + 8 < 24) {
                atomicAdd(&gram_s[(r0 + 8) * 24 + c0], g[mi][ni][2]);
                atomicAdd(&gram_s[(r0 + 8) * 24 + c0 + 1], g[mi][ni][3]);
            }
        }
    }
    __syncthreads();
    for (int e = t; e < CH * CH; e += 128)
        atomicAdd(&g_G[bh * (CH * CH) + e], gram_s[e]);
}

// ---------------- K3: softmax(attn) + M = W_proj @ blockdiag(attn) ----------------
__global__ void __launch_bounds__(192) k3_attn_M(const float* __restrict__ W_proj,
                                                 const float* __restrict__ temperature) {
    __shared__ float attn_s[24 * 24];
    int bh = blockIdx.x;
    int b = bh >> 3;
    int hd = bh & 7;
    int t = threadIdx.x;

    if (t < 24) {
        float inq = 1.f / fmaxf(sqrtf(g_nq[bh * 24 + t]), 1e-12f);
        float temp = temperature[hd];
        float row[24];
        float mx = -1e30f;
#pragma unroll
        for (int d = 0; d < 24; ++d) {
            float ink = 1.f / fmaxf(sqrtf(g_nk[bh * 24 + d]), 1e-12f);
            float v = g_G[bh * (CH * CH) + t * 24 + d] * inq * ink * temp;
            row[d] = v;
            mx = fmaxf(mx, v);
        }
        float sum = 0.f;
#pragma unroll
        for (int d = 0; d < 24; ++d) { row[d] = expf(row[d] - mx); sum += row[d]; }
        float inv = 1.f / sum;
#pragma unroll
        for (int d = 0; d < 24; ++d) attn_s[t * 24 + d] = row[d] * inv;
    }
    __syncthreads();

    float acc[24];
#pragma unroll
    for (int d = 0; d < 24; ++d) acc[d] = 0.f;
#pragma unroll 1
    for (int cl = 0; cl < 24; ++cl) {
        float w = W_proj[(size_t)t * CDIM + hd * CH + cl];
#pragma unroll
        for (int d = 0; d < 24; ++d) acc[d] = fmaf(w, attn_s[cl * 24 + d], acc[d]);
    }
#pragma unroll
    for (int d = 0; d < 24; ++d)
        g_M[((size_t)b * CDIM + t) * CDIM + hd * CH + d] = acc[d];
}

// ---------------- launch ----------------
// Launch order chosen so ncu's fixed capture (our 4th launch) lands on k2_dw_gram.
extern "C" void kernel_launch(void* const* d_in, const int* in_sizes, int n_in,
                              void* d_out, int out_size) {
    const float* x           = (const float*)d_in[0];
    const float* feature     = (const float*)d_in[1];
    const float* W_qkv       = (const float*)d_in[2];
    const float* W_dw        = (const float*)d_in[3];
    const float* W_proj      = (const float*)d_in[4];
    const float* temperature = (const float*)d_in[5];
    float* out = (float*)d_out;

    zero_accum<<<144, 256>>>();

    // K1a: q,k rows (384 x 16384 per batch), single tf32
    dim3 gqk(HW / 128, 6, BATCH);
    gemm_qk<<<gqk, 256>>>(W_qkv, x);

    // K1b: v rows (192 x 16384 per batch), 3xTF32
    dim3 gv(HW / 128, 3, BATCH);
    gemm_triple<<<gv, 256>>>(0, W_qkv + (size_t)384 * CDIM, x, nullptr);

    // K2: depthwise + gram/norm partials + v   (4th launch -> ncu capture)
    dim3 g2(IMGW / 16, IMGH / 8, BATCH * HEADS);
    k2_dw_gram<<<g2, 128>>>(feature, W_dw);

    // K3: softmax + fold proj
    k3_attn_M<<<64, 192>>>(W_proj, temperature);

    // K4: out = M @ v (192 x 16384 per batch), 3xTF32
    dim3 g4(HW / 128, 3, BATCH);
    gemm_triple<<<g4, 256>>>(1, nullptr, nullptr, out);
}